// round 4
// baseline (speedup 1.0000x reference)
#include <cuda_runtime.h>

#define NQ_MAX 131072
#define E_MAX  2097152

// ---------- device scratch (no allocations allowed) ----------
__device__ __align__(16) float g_u[64];        // W^T wq
__device__ __align__(16) float g_v[64];        // W^T wk
__device__ float g_C;                          // proj_b.(wq+wk) + attend_b
__device__ __align__(16) float g_sq[NQ_MAX];   // per-query scalar
__device__ __align__(16) float g_sk[NQ_MAX];   // per-key scalar
__device__ int   g_count[NQ_MAX];
__device__ int   g_off[NQ_MAX + 1];
__device__ int   g_cursor[NQ_MAX];
__device__ int   g_bsum[1024];
__device__ __align__(16) int   g_ski[E_MAX];   // sorted key index
__device__ __align__(16) float g_se[E_MAX];    // sorted logit
__device__ __align__(16) float g_kp[(size_t)NQ_MAX * 64];  // kv_proj

// ---------- kernels ----------
__global__ void k_zero(int n) {
    int i = blockIdx.x * blockDim.x + threadIdx.x;
    if (i < n) g_count[i] = 0;
}

__global__ void k_prep(const float* __restrict__ W, const float* __restrict__ pb,
                       const float* __restrict__ aw, const float* __restrict__ ab) {
    int j = threadIdx.x;
    if (j < 64) {
        float uj = 0.f, vj = 0.f;
        #pragma unroll
        for (int i = 0; i < 64; i++) {
            float w = W[i * 64 + j];
            uj += w * aw[i];
            vj += w * aw[64 + i];
        }
        g_u[j] = uj;
        g_v[j] = vj;
    }
    if (j == 0) {
        float c = ab[0];
        for (int i = 0; i < 64; i++) c += pb[i] * (aw[i] + aw[64 + i]);
        g_C = c;
    }
}

// warp per node row: sq = q . u  (or sk = kv . v)
__global__ void k_node_scalars(const float* __restrict__ q, const float* __restrict__ kv,
                               int Nq, int Nk) {
    int w = (blockIdx.x * blockDim.x + threadIdx.x) >> 5;
    int lane = threadIdx.x & 31;
    if (w >= Nq + Nk) return;
    const float* row; const float* wt; float* dst;
    if (w < Nq) { row = q  + (size_t)w * 64;        wt = g_u; dst = g_sq + w; }
    else        { int m = w - Nq;
                  row = kv + (size_t)m * 64;        wt = g_v; dst = g_sk + m; }
    float2 a = *(const float2*)(row + lane * 2);
    float2 b = *(const float2*)(wt  + lane * 2);
    float acc = a.x * b.x + a.y * b.y;
    #pragma unroll
    for (int o = 16; o; o >>= 1) acc += __shfl_xor_sync(0xffffffffu, acc, o);
    if (lane == 0) *dst = acc;
}

// degree histogram over qi (edge_index row 0)
__global__ void k_edge1(const int* __restrict__ eidx, int E) {
    int j = blockIdx.x * blockDim.x + threadIdx.x;
    if (j >= E) return;
    atomicAdd(&g_count[eidx[j]], 1);
}

// 2-level exclusive scan of g_count -> g_off
__global__ void k_scan_a(int Nq) {
    __shared__ int s[1024];
    int tid = threadIdx.x;
    int i = blockIdx.x * 1024 + tid;
    int x = (i < Nq) ? g_count[i] : 0;
    s[tid] = x; __syncthreads();
    for (int off = 1; off < 1024; off <<= 1) {
        int t = (tid >= off) ? s[tid - off] : 0;
        __syncthreads();
        s[tid] += t; __syncthreads();
    }
    int incl = s[tid];
    if (i < Nq) g_off[i] = incl - x;
    if (tid == 1023) g_bsum[blockIdx.x] = incl;
}

__global__ void k_scan_b(int nb) {
    __shared__ int s[1024];
    int tid = threadIdx.x;
    int x = (tid < nb) ? g_bsum[tid] : 0;
    s[tid] = x; __syncthreads();
    for (int off = 1; off < 1024; off <<= 1) {
        int t = (tid >= off) ? s[tid - off] : 0;
        __syncthreads();
        s[tid] += t; __syncthreads();
    }
    if (tid < nb) g_bsum[tid] = s[tid] - x;
}

__global__ void k_scan_c(int Nq, int E) {
    int i = blockIdx.x * blockDim.x + threadIdx.x;
    if (i < Nq) {
        int off = g_off[i] + g_bsum[i >> 10];
        g_off[i] = off;
        g_cursor[i] = off;
    }
    if (i == 0) g_off[Nq] = E;
}

// counting-sort scatter: compute logit, place (ki, e) into qi-contiguous segment
__global__ void k_scatter(const int* __restrict__ eidx, int E) {
    int j = blockIdx.x * blockDim.x + threadIdx.x;
    if (j >= E) return;
    int qi = eidx[j];
    int ki = eidx[E + j];
    float ev = g_sq[qi] + g_sk[ki] + g_C;
    ev = ev > 0.f ? ev : 0.2f * ev;          // leaky relu, alpha = 0.2
    int pos = atomicAdd(&g_cursor[qi], 1);
    g_ski[pos] = ki;
    g_se[pos] = ev;
}

// kv_proj = kv @ W^T + b   (Nk x 64), 128 rows per block
__global__ void k_gemm(const float* __restrict__ x, const float* __restrict__ W,
                       const float* __restrict__ b, int Nk) {
    __shared__ __align__(16) float Wts[64 * 64];  // Wts[j*64+i] = W[i*64+j]
    __shared__ __align__(16) float xs[16 * 64];
    int tid = threadIdx.x;
    for (int t = tid * 4; t < 4096; t += 1024) {
        float4 w = *(const float4*)(W + t);
        int i = t >> 6, j = t & 63;
        Wts[(j + 0) * 64 + i] = w.x;
        Wts[(j + 1) * 64 + i] = w.y;
        Wts[(j + 2) * 64 + i] = w.z;
        Wts[(j + 3) * 64 + i] = w.w;
    }
    int r  = tid >> 4;   // 0..15 row within tile
    int cg = tid & 15;   // 0..15 column group (4 cols)
    float4 bias = *(const float4*)(b + cg * 4);
    int base = blockIdx.x * 128;
    for (int it = 0; it < 8; it++) {
        __syncthreads();   // covers Wts on it=0, xs reuse otherwise
        int lr = tid >> 4, lj = tid & 15;
        int row_l = base + it * 16 + lr;
        float4 xv4 = (row_l < Nk) ? *(const float4*)(x + (size_t)row_l * 64 + lj * 4)
                                  : make_float4(0.f, 0.f, 0.f, 0.f);
        *(float4*)(xs + lr * 64 + lj * 4) = xv4;
        __syncthreads();
        int row = base + it * 16 + r;
        float4 acc = bias;
        #pragma unroll
        for (int j = 0; j < 64; j++) {
            float  xv = xs[r * 64 + j];
            float4 wv = *(const float4*)(Wts + j * 64 + cg * 4);
            acc.x += xv * wv.x; acc.y += xv * wv.y;
            acc.z += xv * wv.z; acc.w += xv * wv.w;
        }
        if (row < Nk) *(float4*)(g_kp + (size_t)row * 64 + cg * 4) = acc;
    }
}

// warp per query node: segment max -> exp -> sum + weighted accumulate -> normalize
__global__ void k_agg(float* __restrict__ out, int Nq) {
    int w = (blockIdx.x * blockDim.x + threadIdx.x) >> 5;
    int lane = threadIdx.x & 31;
    if (w >= Nq) return;
    int s = g_off[w], e = g_off[w + 1];
    float mx = -3.402823466e38f;
    for (int i = s + lane; i < e; i += 32) mx = fmaxf(mx, g_se[i]);
    #pragma unroll
    for (int o = 16; o; o >>= 1) mx = fmaxf(mx, __shfl_xor_sync(0xffffffffu, mx, o));
    float sum = 0.f, ax = 0.f, ay = 0.f;
    for (int base = s; base < e; base += 32) {
        int i = base + lane;
        float ex = 0.f; int kn = 0;
        if (i < e) { ex = __expf(g_se[i] - mx); kn = g_ski[i]; }
        sum += ex;
        int cnt = min(32, e - base);
        for (int j = 0; j < cnt; j++) {
            float exj = __shfl_sync(0xffffffffu, ex, j);
            int   knj = __shfl_sync(0xffffffffu, kn, j);
            float2 kvv = *(const float2*)(g_kp + (size_t)knj * 64 + lane * 2);
            ax += exj * kvv.x;
            ay += exj * kvv.y;
        }
    }
    #pragma unroll
    for (int o = 16; o; o >>= 1) sum += __shfl_xor_sync(0xffffffffu, sum, o);
    float inv = 1.0f / (sum + 1e-10f);   // EPS from reference
    *(float2*)(out + (size_t)w * 64 + lane * 2) = make_float2(ax * inv, ay * inv);
}

// ---------- launch ----------
extern "C" void kernel_launch(void* const* d_in, const int* in_sizes, int n_in,
                              void* d_out, int out_size) {
    const float* q  = (const float*)d_in[0];      // query_nodes (Nq,64)
    const float* kv = (const float*)d_in[1];      // key_value_nodes (Nk,64)
    const int*   ei = (const int*)d_in[2];        // edge_index (2,E) int32 (JAX x64 off)
    const float* W  = (const float*)d_in[3];      // proj_w (64,64)
    const float* pb = (const float*)d_in[4];      // proj_b (64)
    const float* aw = (const float*)d_in[5];      // attend_w (1,128)
    const float* ab = (const float*)d_in[6];      // attend_b (1)
    float* out = (float*)d_out;

    int Nq = in_sizes[0] / 64;
    int Nk = in_sizes[1] / 64;
    int E  = in_sizes[2] / 2;
    int nb = (Nq + 1023) / 1024;

    k_zero<<<(Nq + 255) / 256, 256>>>(Nq);
    k_prep<<<1, 64>>>(W, pb, aw, ab);
    int nwarp = Nq + Nk;
    k_node_scalars<<<(nwarp + 7) / 8, 256>>>(q, kv, Nq, Nk);
    k_edge1<<<(E + 255) / 256, 256>>>(ei, E);
    k_scan_a<<<nb, 1024>>>(Nq);
    k_scan_b<<<1, 1024>>>(nb);
    k_scan_c<<<(Nq + 255) / 256, 256>>>(Nq, E);
    k_scatter<<<(E + 255) / 256, 256>>>(ei, E);
    k_gemm<<<(Nk + 127) / 128, 256>>>(kv, W, pb, Nk);
    k_agg<<<(Nq + 7) / 8, 256>>>(out, Nq);
}

// round 5
// speedup vs baseline: 1.0409x; 1.0409x over previous
#include <cuda_runtime.h>

#define NQ_MAX 131072
#define E_MAX  2097152

// ---------- device scratch (no allocations allowed) ----------
__device__ __align__(16) float g_u[64];        // W^T wq
__device__ __align__(16) float g_v[64];        // W^T wk
__device__ float g_C;                          // proj_b.(wq+wk) + attend_b
__device__ __align__(16) float g_sq[NQ_MAX];   // per-query scalar
__device__ __align__(16) float g_sk[NQ_MAX];   // per-key scalar
__device__ int   g_count[NQ_MAX];
__device__ int   g_off[NQ_MAX + 1];
__device__ int   g_cursor[NQ_MAX];
__device__ int   g_bsum[1024];
__device__ __align__(16) int2  g_pair[E_MAX];  // sorted (ki, logit bits)
__device__ __align__(16) float g_kp[(size_t)NQ_MAX * 64];  // kv_proj

// ---------- kernels ----------
// zero histogram (whole grid) + compute u, v, C (block 0)
__global__ void k_prep(const float* __restrict__ W, const float* __restrict__ pb,
                       const float* __restrict__ aw, const float* __restrict__ ab,
                       int Nq) {
    int i = blockIdx.x * blockDim.x + threadIdx.x;
    if (i < Nq) g_count[i] = 0;
    if (blockIdx.x == 0) {
        int j = threadIdx.x;
        if (j < 64) {
            float uj = 0.f, vj = 0.f;
            #pragma unroll
            for (int r = 0; r < 64; r++) {
                float w = W[r * 64 + j];
                uj += w * aw[r];
                vj += w * aw[64 + r];
            }
            g_u[j] = uj;
            g_v[j] = vj;
        }
        if (j == 0) {
            float c = ab[0];
            for (int r = 0; r < 64; r++) c += pb[r] * (aw[r] + aw[64 + r]);
            g_C = c;
        }
    }
}

// warp per node row: sq = q . u  (or sk = kv . v)
__global__ void k_node_scalars(const float* __restrict__ q, const float* __restrict__ kv,
                               int Nq, int Nk) {
    int w = (blockIdx.x * blockDim.x + threadIdx.x) >> 5;
    int lane = threadIdx.x & 31;
    if (w >= Nq + Nk) return;
    const float* row; const float* wt; float* dst;
    if (w < Nq) { row = q  + (size_t)w * 64;        wt = g_u; dst = g_sq + w; }
    else        { int m = w - Nq;
                  row = kv + (size_t)m * 64;        wt = g_v; dst = g_sk + m; }
    float2 a = *(const float2*)(row + lane * 2);
    float2 b = *(const float2*)(wt  + lane * 2);
    float acc = a.x * b.x + a.y * b.y;
    #pragma unroll
    for (int o = 16; o; o >>= 1) acc += __shfl_xor_sync(0xffffffffu, acc, o);
    if (lane == 0) *dst = acc;
}

// degree histogram over qi, 4 edges per thread
__global__ void k_edge1(const int* __restrict__ eidx, int E) {
    int j4 = (blockIdx.x * blockDim.x + threadIdx.x) * 4;
    if (j4 + 3 < E) {
        int4 v = *(const int4*)(eidx + j4);
        atomicAdd(&g_count[v.x], 1);
        atomicAdd(&g_count[v.y], 1);
        atomicAdd(&g_count[v.z], 1);
        atomicAdd(&g_count[v.w], 1);
    } else {
        for (int j = j4; j < E; j++) atomicAdd(&g_count[eidx[j]], 1);
    }
}

// 2-level exclusive scan of g_count -> g_off
__global__ void k_scan_a(int Nq) {
    __shared__ int s[1024];
    int tid = threadIdx.x;
    int i = blockIdx.x * 1024 + tid;
    int x = (i < Nq) ? g_count[i] : 0;
    s[tid] = x; __syncthreads();
    for (int off = 1; off < 1024; off <<= 1) {
        int t = (tid >= off) ? s[tid - off] : 0;
        __syncthreads();
        s[tid] += t; __syncthreads();
    }
    int incl = s[tid];
    if (i < Nq) g_off[i] = incl - x;
    if (tid == 1023) g_bsum[blockIdx.x] = incl;
}

__global__ void k_scan_b(int nb) {
    __shared__ int s[1024];
    int tid = threadIdx.x;
    int x = (tid < nb) ? g_bsum[tid] : 0;
    s[tid] = x; __syncthreads();
    for (int off = 1; off < 1024; off <<= 1) {
        int t = (tid >= off) ? s[tid - off] : 0;
        __syncthreads();
        s[tid] += t; __syncthreads();
    }
    if (tid < nb) g_bsum[tid] = s[tid] - x;
}

__global__ void k_scan_c(int Nq, int E) {
    int i = blockIdx.x * blockDim.x + threadIdx.x;
    if (i < Nq) {
        int off = g_off[i] + g_bsum[i >> 10];
        g_off[i] = off;
        g_cursor[i] = off;
    }
    if (i == 0) g_off[Nq] = E;
}

// counting-sort scatter: compute logit, place (ki, e) pair into qi-contiguous
// segment. 2 edges per thread for MLP on the atomic->store chain.
__global__ void k_scatter(const int* __restrict__ eidx, int E) {
    int j2 = (blockIdx.x * blockDim.x + threadIdx.x) * 2;
    if (((E & 1) == 0) && (j2 + 1 < E)) {
        int2 qq = *(const int2*)(eidx + j2);
        int2 kk = *(const int2*)(eidx + E + j2);
        float e0 = g_sq[qq.x] + g_sk[kk.x] + g_C;
        float e1 = g_sq[qq.y] + g_sk[kk.y] + g_C;
        e0 = e0 > 0.f ? e0 : 0.2f * e0;
        e1 = e1 > 0.f ? e1 : 0.2f * e1;
        int p0 = atomicAdd(&g_cursor[qq.x], 1);
        int p1 = atomicAdd(&g_cursor[qq.y], 1);
        g_pair[p0] = make_int2(kk.x, __float_as_int(e0));
        g_pair[p1] = make_int2(kk.y, __float_as_int(e1));
    } else {
        for (int j = j2; j < E && j < j2 + 2; j++) {
            int qi = eidx[j];
            int ki = eidx[E + j];
            float ev = g_sq[qi] + g_sk[ki] + g_C;
            ev = ev > 0.f ? ev : 0.2f * ev;
            int pos = atomicAdd(&g_cursor[qi], 1);
            g_pair[pos] = make_int2(ki, __float_as_int(ev));
        }
    }
}

// kv_proj = kv @ W^T + b   (Nk x 64), 128 rows per block
__global__ void k_gemm(const float* __restrict__ x, const float* __restrict__ W,
                       const float* __restrict__ b, int Nk) {
    __shared__ __align__(16) float Wts[64 * 64];  // Wts[j*64+i] = W[i*64+j]
    __shared__ __align__(16) float xs[16 * 64];
    int tid = threadIdx.x;
    for (int t = tid * 4; t < 4096; t += 1024) {
        float4 w = *(const float4*)(W + t);
        int i = t >> 6, j = t & 63;
        Wts[(j + 0) * 64 + i] = w.x;
        Wts[(j + 1) * 64 + i] = w.y;
        Wts[(j + 2) * 64 + i] = w.z;
        Wts[(j + 3) * 64 + i] = w.w;
    }
    int r  = tid >> 4;   // 0..15 row within tile
    int cg = tid & 15;   // 0..15 column group (4 cols)
    float4 bias = *(const float4*)(b + cg * 4);
    int base = blockIdx.x * 128;
    for (int it = 0; it < 8; it++) {
        __syncthreads();   // covers Wts on it=0, xs reuse otherwise
        int lr = tid >> 4, lj = tid & 15;
        int row_l = base + it * 16 + lr;
        float4 xv4 = (row_l < Nk) ? *(const float4*)(x + (size_t)row_l * 64 + lj * 4)
                                  : make_float4(0.f, 0.f, 0.f, 0.f);
        *(float4*)(xs + lr * 64 + lj * 4) = xv4;
        __syncthreads();
        int row = base + it * 16 + r;
        float4 acc = bias;
        #pragma unroll
        for (int j = 0; j < 64; j++) {
            float  xv = xs[r * 64 + j];
            float4 wv = *(const float4*)(Wts + j * 64 + cg * 4);
            acc.x += xv * wv.x; acc.y += xv * wv.y;
            acc.z += xv * wv.z; acc.w += xv * wv.w;
        }
        if (row < Nk) *(float4*)(g_kp + (size_t)row * 64 + cg * 4) = acc;
    }
}

// warp per query node: segment max -> exp -> sum + weighted accumulate -> normalize
__global__ void k_agg(float* __restrict__ out, int Nq) {
    int w = (blockIdx.x * blockDim.x + threadIdx.x) >> 5;
    int lane = threadIdx.x & 31;
    if (w >= Nq) return;
    int s = g_off[w], e = g_off[w + 1];
    float mx = -3.402823466e38f;
    for (int i = s + lane; i < e; i += 32)
        mx = fmaxf(mx, __int_as_float(g_pair[i].y));
    #pragma unroll
    for (int o = 16; o; o >>= 1) mx = fmaxf(mx, __shfl_xor_sync(0xffffffffu, mx, o));
    float sum = 0.f, ax = 0.f, ay = 0.f;
    for (int base = s; base < e; base += 32) {
        int i = base + lane;
        float ex = 0.f; int kn = 0;
        if (i < e) {
            int2 p = g_pair[i];
            kn = p.x;
            ex = __expf(__int_as_float(p.y) - mx);
        }
        sum += ex;
        int cnt = min(32, e - base);
        int j = 0;
        for (; j + 1 < cnt; j += 2) {
            float e0 = __shfl_sync(0xffffffffu, ex, j);
            float e1 = __shfl_sync(0xffffffffu, ex, j + 1);
            int   k0 = __shfl_sync(0xffffffffu, kn, j);
            int   k1 = __shfl_sync(0xffffffffu, kn, j + 1);
            float2 v0 = *(const float2*)(g_kp + (size_t)k0 * 64 + lane * 2);
            float2 v1 = *(const float2*)(g_kp + (size_t)k1 * 64 + lane * 2);
            ax += e0 * v0.x; ay += e0 * v0.y;
            ax += e1 * v1.x; ay += e1 * v1.y;
        }
        if (j < cnt) {
            float e0 = __shfl_sync(0xffffffffu, ex, j);
            int   k0 = __shfl_sync(0xffffffffu, kn, j);
            float2 v0 = *(const float2*)(g_kp + (size_t)k0 * 64 + lane * 2);
            ax += e0 * v0.x; ay += e0 * v0.y;
        }
    }
    #pragma unroll
    for (int o = 16; o; o >>= 1) sum += __shfl_xor_sync(0xffffffffu, sum, o);
    float inv = 1.0f / (sum + 1e-10f);   // EPS from reference
    *(float2*)(out + (size_t)w * 64 + lane * 2) = make_float2(ax * inv, ay * inv);
}

// ---------- launch ----------
extern "C" void kernel_launch(void* const* d_in, const int* in_sizes, int n_in,
                              void* d_out, int out_size) {
    const float* q  = (const float*)d_in[0];      // query_nodes (Nq,64)
    const float* kv = (const float*)d_in[1];      // key_value_nodes (Nk,64)
    const int*   ei = (const int*)d_in[2];        // edge_index (2,E) int32
    const float* W  = (const float*)d_in[3];      // proj_w (64,64)
    const float* pb = (const float*)d_in[4];      // proj_b (64)
    const float* aw = (const float*)d_in[5];      // attend_w (1,128)
    const float* ab = (const float*)d_in[6];      // attend_b (1)
    float* out = (float*)d_out;

    int Nq = in_sizes[0] / 64;
    int Nk = in_sizes[1] / 64;
    int E  = in_sizes[2] / 2;
    int nb = (Nq + 1023) / 1024;

    k_prep<<<(Nq + 255) / 256, 256>>>(W, pb, aw, ab, Nq);
    int nwarp = Nq + Nk;
    k_node_scalars<<<(nwarp + 7) / 8, 256>>>(q, kv, Nq, Nk);
    k_edge1<<<(E / 4 + 255) / 256, 256>>>(ei, E);
    k_scan_a<<<nb, 1024>>>(Nq);
    k_scan_b<<<1, 1024>>>(nb);
    k_scan_c<<<(Nq + 255) / 256, 256>>>(Nq, E);
    k_scatter<<<(E / 2 + 255) / 256, 256>>>(ei, E);
    k_gemm<<<(Nk + 127) / 128, 256>>>(kv, W, pb, Nk);
    k_agg<<<(Nq + 7) / 8, 256>>>(out, Nq);
}